// round 14
// baseline (speedup 1.0000x reference)
#include <cuda_runtime.h>
#include <cuda_bf16.h>
#include <math_constants.h>
#include <cstdint>

#define Bz   16
#define Cch  128
#define Nn   4096
#define Mm   1024
#define LOG2E 1.4426950408889634f

// Scratch (allocation-free rule)
__device__ float d_theta[Bz * 16 * Nn];            // [B,16,N] tf32, pre-scaled by log2e
__device__ float d_phi  [Bz * 16 * Mm];            // [B,16,M] tf32
__device__ __nv_bfloat16 d_gh[Bz * 64 * Mm];       // [B,64,M] bf16
__device__ float d_obuf [Bz * 64 * Nn];            // [B,64,N] fp32

__device__ __forceinline__ float tf32r(float v) {
    uint32_t u;
    asm("cvt.rna.tf32.f32 %0, %1;" : "=r"(u) : "f"(v));
    return __uint_as_float(u);
}
__device__ __forceinline__ float ex2(float v) {
    float r;
    asm("ex2.approx.f32 %0, %1;" : "=f"(r) : "f"(v));
    return r;
}

#define CP_ASYNC16(dst_u32, src_ptr)                                          \
    asm volatile("cp.async.cg.shared.global [%0], [%1], 16;"                  \
        :: "r"(dst_u32), "l"(src_ptr))
#define CP_COMMIT() asm volatile("cp.async.commit_group;")
#define CP_WAIT(n)  asm volatile("cp.async.wait_group %0;" :: "n"(n))

#define MMA_TF32(C0,C1,C2,C3,A0,A1,A2,A3,B0,B1)                               \
    asm volatile("mma.sync.aligned.m16n8k8.row.col.f32.tf32.tf32.f32 "        \
        "{%0,%1,%2,%3}, {%4,%5,%6,%7}, {%8,%9}, {%0,%1,%2,%3};"               \
        : "+f"(C0), "+f"(C1), "+f"(C2), "+f"(C3)                              \
        : "r"(A0), "r"(A1), "r"(A2), "r"(A3), "r"(B0), "r"(B1))

#define MMA_BF16(C0,C1,C2,C3,A0,A1,A2,A3,B0,B1)                               \
    asm volatile("mma.sync.aligned.m16n8k16.row.col.f32.bf16.bf16.f32 "       \
        "{%0,%1,%2,%3}, {%4,%5,%6,%7}, {%8,%9}, {%0,%1,%2,%3};"               \
        : "+f"(C0), "+f"(C1), "+f"(C2), "+f"(C3)                              \
        : "r"(A0), "r"(A1), "r"(A2), "r"(A3), "r"(B0), "r"(B1))

// ---------------------------------------------------------------------------
// Kernel 1: 1x1 convs as tf32 mma GEMM + in-register 2x2 maxpool.
// 192 thr (6 warps), warp = m16 tile of 96 outputs, n = 128 pixels.
// K=128 in four 32-row chunks, cp.async double-buffered (issued 2 ahead).
// ---------------------------------------------------------------------------
__global__ __launch_bounds__(192) void conv_kernel(
    const float* __restrict__ x,
    const float* __restrict__ w_theta,
    const float* __restrict__ w_phi,
    const float* __restrict__ w_g)
{
    extern __shared__ __align__(16) float cs[];
    float* Ws = cs;                 // [96][132]
    float* Xs = cs + 96 * 132;      // [2][32][136]

    const int t  = threadIdx.x;
    const int b  = blockIdx.y;
    const int bx = blockIdx.x;
    const int n0 = bx * 128;

    // stage weights (theta rows pre-scaled by log2e), tf32-rounded
    for (int i = t; i < 96 * 128; i += 192) {
        int m = i >> 7, k = i & 127;
        float v;
        if (m < 16)      v = w_theta[m * 128 + k] * LOG2E;
        else if (m < 32) v = w_phi[(m - 16) * 128 + k];
        else             v = w_g[(m - 32) * 128 + k];
        Ws[m * 132 + k] = tf32r(v);
    }

    const uint32_t xs_base =
        (uint32_t)__cvta_generic_to_shared(Xs);

    // issue chunk kc (32 k-rows) into buffer buf
    auto issue = [&](int kc, int buf) {
        const float* src = x + (size_t)(b * Cch + kc * 32) * Nn + n0;
        for (int i = t; i < 32 * 32; i += 192) {      // 1024 float4
            int kk = i >> 5, p4 = i & 31;
            uint32_t dst = xs_base + (uint32_t)(buf * (32 * 136) + kk * 136 + p4 * 4) * 4u;
            CP_ASYNC16(dst, src + (size_t)kk * Nn + p4 * 4);
        }
        CP_COMMIT();
    };
    issue(0, 0);
    issue(1, 1);

    const int w    = t >> 5;
    const int lane = t & 31;
    const int g4   = lane >> 2;
    const int t2   = lane & 3;
    const int m0   = w * 16;

    float acc[16][4];
#pragma unroll
    for (int j = 0; j < 16; j++)
#pragma unroll
        for (int q = 0; q < 4; q++) acc[j][q] = 0.f;

#pragma unroll
    for (int kc = 0; kc < 4; kc++) {
        if (kc < 3) { CP_WAIT(1); } else { CP_WAIT(0); }
        __syncthreads();
        const float* Xb = Xs + (kc & 1) * (32 * 136);

#pragma unroll
        for (int ks = 0; ks < 4; ks++) {
            const int krow = kc * 32 + ks * 8;
            uint32_t a0 = __float_as_uint(Ws[(m0 + g4)     * 132 + krow + t2]);
            uint32_t a1 = __float_as_uint(Ws[(m0 + g4 + 8) * 132 + krow + t2]);
            uint32_t a2 = __float_as_uint(Ws[(m0 + g4)     * 132 + krow + t2 + 4]);
            uint32_t a3 = __float_as_uint(Ws[(m0 + g4 + 8) * 132 + krow + t2 + 4]);
#pragma unroll
            for (int j = 0; j < 16; j++) {
                uint32_t b0 = __float_as_uint(Xb[(ks * 8 + t2)     * 136 + j * 8 + g4]);
                uint32_t b1 = __float_as_uint(Xb[(ks * 8 + t2 + 4) * 136 + j * 8 + g4]);
                MMA_TF32(acc[j][0], acc[j][1], acc[j][2], acc[j][3],
                         a0, a1, a2, a3, b0, b1);
            }
        }
        __syncthreads();
        if (kc + 2 < 4) issue(kc + 2, kc & 1);
    }

    // epilogue: C[m0+g4][j*8+2t2 .. +1] = acc[j][0..1]; rows +8 -> acc[j][2..3]
    if (w == 0) {  // theta
#pragma unroll
        for (int j = 0; j < 16; j++) {
            size_t p = (size_t)(b * 16 + g4) * Nn + n0 + j * 8 + 2 * t2;
            *(float2*)&d_theta[p] = make_float2(tf32r(acc[j][0]), tf32r(acc[j][1]));
            size_t p2 = (size_t)(b * 16 + g4 + 8) * Nn + n0 + j * 8 + 2 * t2;
            *(float2*)&d_theta[p2] = make_float2(tf32r(acc[j][2]), tf32r(acc[j][3]));
        }
    } else {       // phi/g: 2x2 pool in-register
#pragma unroll
        for (int j = 0; j < 8; j++) {
            float pr0 = fmaxf(fmaxf(acc[j][0], acc[j][1]),
                              fmaxf(acc[j + 8][0], acc[j + 8][1]));
            float pr1 = fmaxf(fmaxf(acc[j][2], acc[j][3]),
                              fmaxf(acc[j + 8][2], acc[j + 8][3]));
            int pm = bx * 32 + j * 4 + t2;
            if (w == 1) {
                d_phi[(size_t)(b * 16 + g4)     * Mm + pm] = tf32r(pr0);
                d_phi[(size_t)(b * 16 + g4 + 8) * Mm + pm] = tf32r(pr1);
            } else {
                int c = (w - 2) * 16 + g4;
                d_gh[(size_t)(b * 64 + c)     * Mm + pm] = __float2bfloat16(pr0);
                d_gh[(size_t)(b * 64 + c + 8) * Mm + pm] = __float2bfloat16(pr1);
            }
        }
    }
}

// ---------------------------------------------------------------------------
// Kernel 2: attention. QK^T tf32 mma, p = ex2(s), PV bf16 m16n8k16.
// M in 16 chunks of 64, cp.async double-buffered phi/g.
// ---------------------------------------------------------------------------
__global__ __launch_bounds__(256) void attn_kernel()
{
    __shared__ __align__(16) float    phi_sm[2][16 * 72];
    __shared__ __align__(16) uint32_t g_smh [2][64 * 36];
    __shared__ __align__(16) uint32_t p_smh [128 * 36];

    const int b    = blockIdx.y;
    const int n0   = blockIdx.x * 128;
    const int t    = threadIdx.x;
    const int w    = t >> 5;
    const int lane = t & 31;
    const int g4   = lane >> 2;
    const int t2   = lane & 3;
    const int row0 = w * 16 + g4;

    const uint32_t phi_base = (uint32_t)__cvta_generic_to_shared(&phi_sm[0][0]);
    const uint32_t g_base   = (uint32_t)__cvta_generic_to_shared(&g_smh[0][0]);

    auto issue = [&](int mc, int buf) {
        // phi chunk: 16 rows x 64 floats = 256 float4
        {
            int i = t;                       // 256 threads -> exactly 1 each
            int k = i >> 4, m4 = i & 15;
            uint32_t dst = phi_base + (uint32_t)(buf * (16 * 72) + k * 72 + m4 * 4) * 4u;
            CP_ASYNC16(dst, d_phi + (size_t)(b * 16 + k) * Mm + mc * 64 + m4 * 4);
        }
        // g chunk: 64 rows x 32 u32 = 512 x 16B
        for (int i = t; i < 512; i += 256) {
            int c = i >> 3, q4 = i & 7;
            uint32_t dst = g_base + (uint32_t)(buf * (64 * 36) + c * 36 + q4 * 4) * 4u;
            CP_ASYNC16(dst, (const char*)(d_gh + (size_t)(b * 64 + c) * Mm + mc * 64) + q4 * 16);
        }
        CP_COMMIT();
    };
    issue(0, 0);
    issue(1, 1);

    // Q fragments (tf32), persist across M loop
    uint32_t qa[2][4];
    const float* tb = d_theta + (size_t)(b * 16) * Nn + n0;
#pragma unroll
    for (int ks = 0; ks < 2; ks++) {
        int k0 = ks * 8 + t2;
        qa[ks][0] = __float_as_uint(tb[(size_t)k0 * Nn + row0]);
        qa[ks][1] = __float_as_uint(tb[(size_t)k0 * Nn + row0 + 8]);
        qa[ks][2] = __float_as_uint(tb[(size_t)(k0 + 4) * Nn + row0]);
        qa[ks][3] = __float_as_uint(tb[(size_t)(k0 + 4) * Nn + row0 + 8]);
    }

    float o[8][4];
#pragma unroll
    for (int i = 0; i < 8; i++)
#pragma unroll
        for (int q = 0; q < 4; q++) o[i][q] = 0.f;
    float rs0 = 0.f, rs1 = 0.f;

    for (int mc = 0; mc < 16; mc++) {
        if (mc < 15) { CP_WAIT(1); } else { CP_WAIT(0); }
        __syncthreads();
        const float*    phb = phi_sm[mc & 1];
        const uint32_t* gb  = g_smh[mc & 1];

        // scores + exp + pack P to bf16 pairs
#pragma unroll
        for (int mt = 0; mt < 8; mt++) {
            float s0 = 0.f, s1 = 0.f, s2 = 0.f, s3 = 0.f;
#pragma unroll
            for (int ks = 0; ks < 2; ks++) {
                uint32_t b0 = __float_as_uint(phb[(ks*8 + t2)     * 72 + mt*8 + g4]);
                uint32_t b1 = __float_as_uint(phb[(ks*8 + t2 + 4) * 72 + mt*8 + g4]);
                MMA_TF32(s0, s1, s2, s3, qa[ks][0], qa[ks][1], qa[ks][2], qa[ks][3], b0, b1);
            }
            float p0 = ex2(s0), p1 = ex2(s1), p2 = ex2(s2), p3 = ex2(s3);
            rs0 += p0 + p1;
            rs1 += p2 + p3;
            __nv_bfloat162 h01 = __float22bfloat162_rn(make_float2(p0, p1));
            __nv_bfloat162 h23 = __float22bfloat162_rn(make_float2(p2, p3));
            p_smh[(size_t)row0       * 36 + mt * 4 + t2] = *reinterpret_cast<uint32_t*>(&h01);
            p_smh[(size_t)(row0 + 8) * 36 + mt * 4 + t2] = *reinterpret_cast<uint32_t*>(&h23);
        }
        __syncwarp();

        // O += P V  (bf16; P rows warp-private)
#pragma unroll
        for (int ms = 0; ms < 4; ms++) {
            uint32_t a0 = p_smh[(size_t)row0       * 36 + ms * 8 + t2];
            uint32_t a1 = p_smh[(size_t)(row0 + 8) * 36 + ms * 8 + t2];
            uint32_t a2 = p_smh[(size_t)row0       * 36 + ms * 8 + t2 + 4];
            uint32_t a3 = p_smh[(size_t)(row0 + 8) * 36 + ms * 8 + t2 + 4];
#pragma unroll
            for (int ct = 0; ct < 8; ct++) {
                uint32_t b0 = gb[(ct * 8 + g4) * 36 + ms * 8 + t2];
                uint32_t b1 = gb[(ct * 8 + g4) * 36 + ms * 8 + t2 + 4];
                MMA_BF16(o[ct][0], o[ct][1], o[ct][2], o[ct][3],
                         a0, a1, a2, a3, b0, b1);
            }
        }
        __syncthreads();
        if (mc + 2 < 16) issue(mc + 2, mc & 1);
    }

    rs0 += __shfl_xor_sync(0xffffffffu, rs0, 1);
    rs0 += __shfl_xor_sync(0xffffffffu, rs0, 2);
    rs1 += __shfl_xor_sync(0xffffffffu, rs1, 1);
    rs1 += __shfl_xor_sync(0xffffffffu, rs1, 2);
    const float inv0 = 1.f / rs0, inv1 = 1.f / rs1;

#pragma unroll
    for (int ct = 0; ct < 8; ct++) {
        int c = ct * 8 + 2 * t2;
        size_t base = (size_t)(b * 64 + c) * Nn + n0 + row0;
        d_obuf[base]          = o[ct][0] * inv0;
        d_obuf[base + Nn]     = o[ct][1] * inv0;
        d_obuf[base + 8]      = o[ct][2] * inv1;
        d_obuf[base + Nn + 8] = o[ct][3] * inv1;
    }
}

// ---------------------------------------------------------------------------
// Kernel 3: out = gamma * (w_o @ o) + x.
// ---------------------------------------------------------------------------
__global__ __launch_bounds__(256) void out_kernel(
    const float* __restrict__ x,
    const float* __restrict__ w_o,
    const float* __restrict__ gamma,
    float* __restrict__ out)
{
    __shared__ __align__(16) float wt_sm[64 * 128];
    __shared__ __align__(16) float o_sm [64 * 64];
    const int t  = threadIdx.x;
    const int tx = t & 15;
    const int ty = t >> 4;
    const int b   = blockIdx.y;
    const int px0 = blockIdx.x * 64;

    for (int i = t; i < 8192; i += 256) {
        int k = i & 127, c = i >> 7;
        wt_sm[c * 128 + k] = w_o[k * 64 + c];
    }
    for (int i = t; i < 1024; i += 256) {
        int c = i >> 4, p4 = i & 15;
        *(float4*)&o_sm[c * 64 + p4 * 4] =
            *(const float4*)&d_obuf[(size_t)(b * 64 + c) * Nn + px0 + p4 * 4];
    }
    __syncthreads();

    float acc[8][4];
#pragma unroll
    for (int i = 0; i < 8; i++)
#pragma unroll
        for (int q = 0; q < 4; q++) acc[i][q] = 0.f;

    const float4* o4 = (const float4*)o_sm;
    const float4* w4 = (const float4*)wt_sm;

    for (int c = 0; c < 64; c++) {
        float4 ov = o4[c * 16 + tx];
        float4 wa = w4[c * 32 + ty * 2];
        float4 wb = w4[c * 32 + ty * 2 + 1];
        const float wv[8] = {wa.x, wa.y, wa.z, wa.w, wb.x, wb.y, wb.z, wb.w};
#pragma unroll
        for (int i = 0; i < 8; i++) {
            acc[i][0] = fmaf(wv[i], ov.x, acc[i][0]);
            acc[i][1] = fmaf(wv[i], ov.y, acc[i][1]);
            acc[i][2] = fmaf(wv[i], ov.z, acc[i][2]);
            acc[i][3] = fmaf(wv[i], ov.w, acc[i][3]);
        }
    }

    const float gm = gamma[0];
#pragma unroll
    for (int i = 0; i < 8; i++) {
        size_t idx = (size_t)(b * 128 + ty * 8 + i) * Nn + px0 + tx * 4;
        float4 xv = *(const float4*)(x + idx);
        float4 rv;
        rv.x = fmaf(gm, acc[i][0], xv.x);
        rv.y = fmaf(gm, acc[i][1], xv.y);
        rv.z = fmaf(gm, acc[i][2], xv.z);
        rv.w = fmaf(gm, acc[i][3], xv.w);
        *(float4*)(out + idx) = rv;
    }
}

// ---------------------------------------------------------------------------
extern "C" void kernel_launch(void* const* d_in, const int* in_sizes, int n_in,
                              void* d_out, int out_size)
{
    const float* x       = (const float*)d_in[0];
    const float* w_theta = (const float*)d_in[1];
    const float* w_phi   = (const float*)d_in[2];
    const float* w_g     = (const float*)d_in[3];
    const float* w_o     = (const float*)d_in[4];
    const float* gamma   = (const float*)d_in[5];
    float* out = (float*)d_out;

    const int conv_smem = (96 * 132 + 2 * 32 * 136) * (int)sizeof(float);
    static bool attr_set = false;
    if (!attr_set) {
        cudaFuncSetAttribute(conv_kernel,
                             cudaFuncAttributeMaxDynamicSharedMemorySize, conv_smem);
        attr_set = true;
    }

    conv_kernel<<<dim3(32, Bz), 192, conv_smem>>>(x, w_theta, w_phi, w_g);
    attn_kernel<<<dim3(Nn / 128, Bz), 256>>>();
    out_kernel<<<dim3(Nn / 64, Bz), 256>>>(x, w_o, gamma, out);
}

// round 15
// speedup vs baseline: 1.0104x; 1.0104x over previous
#include <cuda_runtime.h>
#include <cuda_bf16.h>
#include <math_constants.h>
#include <cstdint>

#define Bz   16
#define Cch  128
#define Nn   4096
#define Mm   1024
#define LOG2E 1.4426950408889634f

// Scratch (allocation-free rule)
__device__ float d_theta[Bz * 16 * Nn];            // [B,16,N] tf32, pre-scaled by log2e
__device__ float d_phi  [Bz * 16 * Mm];            // [B,16,M] tf32
__device__ __nv_bfloat16 d_gh[Bz * 64 * Mm];       // [B,64,M] bf16
__device__ float d_obuf [Bz * 64 * Nn];            // [B,64,N] fp32

__device__ __forceinline__ float tf32r(float v) {
    uint32_t u;
    asm("cvt.rna.tf32.f32 %0, %1;" : "=r"(u) : "f"(v));
    return __uint_as_float(u);
}
__device__ __forceinline__ float ex2(float v) {
    float r;
    asm("ex2.approx.f32 %0, %1;" : "=f"(r) : "f"(v));
    return r;
}

#define CP_ASYNC16(dst_u32, src_ptr)                                          \
    asm volatile("cp.async.cg.shared.global [%0], [%1], 16;"                  \
        :: "r"(dst_u32), "l"(src_ptr))
#define CP_COMMIT() asm volatile("cp.async.commit_group;")
#define CP_WAIT(n)  asm volatile("cp.async.wait_group %0;" :: "n"(n))

#define MMA_TF32(C0,C1,C2,C3,A0,A1,A2,A3,B0,B1)                               \
    asm volatile("mma.sync.aligned.m16n8k8.row.col.f32.tf32.tf32.f32 "        \
        "{%0,%1,%2,%3}, {%4,%5,%6,%7}, {%8,%9}, {%0,%1,%2,%3};"               \
        : "+f"(C0), "+f"(C1), "+f"(C2), "+f"(C3)                              \
        : "r"(A0), "r"(A1), "r"(A2), "r"(A3), "r"(B0), "r"(B1))

#define MMA_BF16(C0,C1,C2,C3,A0,A1,A2,A3,B0,B1)                               \
    asm volatile("mma.sync.aligned.m16n8k16.row.col.f32.bf16.bf16.f32 "       \
        "{%0,%1,%2,%3}, {%4,%5,%6,%7}, {%8,%9}, {%0,%1,%2,%3};"               \
        : "+f"(C0), "+f"(C1), "+f"(C2), "+f"(C3)                              \
        : "r"(A0), "r"(A1), "r"(A2), "r"(A3), "r"(B0), "r"(B1))

// ---------------------------------------------------------------------------
// Kernel 1: 1x1 convs as tf32 mma GEMM + in-register 2x2 maxpool.
// 192 thr (6 warps), warp = m16 tile of 96 outputs, n = 128 pixels.
// K=128 in four 32-row chunks, cp.async double-buffered (issued 2 ahead).
// ---------------------------------------------------------------------------
__global__ __launch_bounds__(192) void conv_kernel(
    const float* __restrict__ x,
    const float* __restrict__ w_theta,
    const float* __restrict__ w_phi,
    const float* __restrict__ w_g)
{
    extern __shared__ __align__(16) float cs[];
    float* Ws = cs;                 // [96][132]
    float* Xs = cs + 96 * 132;      // [2][32][136]

    const int t  = threadIdx.x;
    const int b  = blockIdx.y;
    const int bx = blockIdx.x;
    const int n0 = bx * 128;

    // stage weights (theta rows pre-scaled by log2e), tf32-rounded
    for (int i = t; i < 96 * 128; i += 192) {
        int m = i >> 7, k = i & 127;
        float v;
        if (m < 16)      v = w_theta[m * 128 + k] * LOG2E;
        else if (m < 32) v = w_phi[(m - 16) * 128 + k];
        else             v = w_g[(m - 32) * 128 + k];
        Ws[m * 132 + k] = tf32r(v);
    }

    const uint32_t xs_base =
        (uint32_t)__cvta_generic_to_shared(Xs);

    // issue chunk kc (32 k-rows) into buffer buf
    auto issue = [&](int kc, int buf) {
        const float* src = x + (size_t)(b * Cch + kc * 32) * Nn + n0;
        for (int i = t; i < 32 * 32; i += 192) {      // 1024 float4
            int kk = i >> 5, p4 = i & 31;
            uint32_t dst = xs_base + (uint32_t)(buf * (32 * 136) + kk * 136 + p4 * 4) * 4u;
            CP_ASYNC16(dst, src + (size_t)kk * Nn + p4 * 4);
        }
        CP_COMMIT();
    };
    issue(0, 0);
    issue(1, 1);

    const int w    = t >> 5;
    const int lane = t & 31;
    const int g4   = lane >> 2;
    const int t2   = lane & 3;
    const int m0   = w * 16;

    float acc[16][4];
#pragma unroll
    for (int j = 0; j < 16; j++)
#pragma unroll
        for (int q = 0; q < 4; q++) acc[j][q] = 0.f;

#pragma unroll
    for (int kc = 0; kc < 4; kc++) {
        if (kc < 3) { CP_WAIT(1); } else { CP_WAIT(0); }
        __syncthreads();
        const float* Xb = Xs + (kc & 1) * (32 * 136);

#pragma unroll
        for (int ks = 0; ks < 4; ks++) {
            const int krow = kc * 32 + ks * 8;
            uint32_t a0 = __float_as_uint(Ws[(m0 + g4)     * 132 + krow + t2]);
            uint32_t a1 = __float_as_uint(Ws[(m0 + g4 + 8) * 132 + krow + t2]);
            uint32_t a2 = __float_as_uint(Ws[(m0 + g4)     * 132 + krow + t2 + 4]);
            uint32_t a3 = __float_as_uint(Ws[(m0 + g4 + 8) * 132 + krow + t2 + 4]);
#pragma unroll
            for (int j = 0; j < 16; j++) {
                uint32_t b0 = __float_as_uint(Xb[(ks * 8 + t2)     * 136 + j * 8 + g4]);
                uint32_t b1 = __float_as_uint(Xb[(ks * 8 + t2 + 4) * 136 + j * 8 + g4]);
                MMA_TF32(acc[j][0], acc[j][1], acc[j][2], acc[j][3],
                         a0, a1, a2, a3, b0, b1);
            }
        }
        __syncthreads();
        if (kc + 2 < 4) issue(kc + 2, kc & 1);
    }

    // epilogue: C[m0+g4][j*8+2t2 .. +1] = acc[j][0..1]; rows +8 -> acc[j][2..3]
    if (w == 0) {  // theta
#pragma unroll
        for (int j = 0; j < 16; j++) {
            size_t p = (size_t)(b * 16 + g4) * Nn + n0 + j * 8 + 2 * t2;
            *(float2*)&d_theta[p] = make_float2(tf32r(acc[j][0]), tf32r(acc[j][1]));
            size_t p2 = (size_t)(b * 16 + g4 + 8) * Nn + n0 + j * 8 + 2 * t2;
            *(float2*)&d_theta[p2] = make_float2(tf32r(acc[j][2]), tf32r(acc[j][3]));
        }
    } else {       // phi/g: 2x2 pool in-register
#pragma unroll
        for (int j = 0; j < 8; j++) {
            float pr0 = fmaxf(fmaxf(acc[j][0], acc[j][1]),
                              fmaxf(acc[j + 8][0], acc[j + 8][1]));
            float pr1 = fmaxf(fmaxf(acc[j][2], acc[j][3]),
                              fmaxf(acc[j + 8][2], acc[j + 8][3]));
            int pm = bx * 32 + j * 4 + t2;
            if (w == 1) {
                d_phi[(size_t)(b * 16 + g4)     * Mm + pm] = tf32r(pr0);
                d_phi[(size_t)(b * 16 + g4 + 8) * Mm + pm] = tf32r(pr1);
            } else {
                int c = (w - 2) * 16 + g4;
                d_gh[(size_t)(b * 64 + c)     * Mm + pm] = __float2bfloat16(pr0);
                d_gh[(size_t)(b * 64 + c + 8) * Mm + pm] = __float2bfloat16(pr1);
            }
        }
    }
}

// ---------------------------------------------------------------------------
// Kernel 2: attention. QK^T tf32 mma, p = ex2(s), PV bf16 m16n8k16.
// M in 16 chunks of 64, cp.async double-buffered phi/g.
// ---------------------------------------------------------------------------
__global__ __launch_bounds__(256) void attn_kernel()
{
    __shared__ __align__(16) float    phi_sm[2][16 * 72];
    __shared__ __align__(16) uint32_t g_smh [2][64 * 36];
    __shared__ __align__(16) uint32_t p_smh [128 * 36];

    const int b    = blockIdx.y;
    const int n0   = blockIdx.x * 128;
    const int t    = threadIdx.x;
    const int w    = t >> 5;
    const int lane = t & 31;
    const int g4   = lane >> 2;
    const int t2   = lane & 3;
    const int row0 = w * 16 + g4;

    const uint32_t phi_base = (uint32_t)__cvta_generic_to_shared(&phi_sm[0][0]);
    const uint32_t g_base   = (uint32_t)__cvta_generic_to_shared(&g_smh[0][0]);

    auto issue = [&](int mc, int buf) {
        // phi chunk: 16 rows x 64 floats = 256 float4
        {
            int i = t;                       // 256 threads -> exactly 1 each
            int k = i >> 4, m4 = i & 15;
            uint32_t dst = phi_base + (uint32_t)(buf * (16 * 72) + k * 72 + m4 * 4) * 4u;
            CP_ASYNC16(dst, d_phi + (size_t)(b * 16 + k) * Mm + mc * 64 + m4 * 4);
        }
        // g chunk: 64 rows x 32 u32 = 512 x 16B
        for (int i = t; i < 512; i += 256) {
            int c = i >> 3, q4 = i & 7;
            uint32_t dst = g_base + (uint32_t)(buf * (64 * 36) + c * 36 + q4 * 4) * 4u;
            CP_ASYNC16(dst, (const char*)(d_gh + (size_t)(b * 64 + c) * Mm + mc * 64) + q4 * 16);
        }
        CP_COMMIT();
    };
    issue(0, 0);
    issue(1, 1);

    // Q fragments (tf32), persist across M loop
    uint32_t qa[2][4];
    const float* tb = d_theta + (size_t)(b * 16) * Nn + n0;
#pragma unroll
    for (int ks = 0; ks < 2; ks++) {
        int k0 = ks * 8 + t2;
        qa[ks][0] = __float_as_uint(tb[(size_t)k0 * Nn + row0]);
        qa[ks][1] = __float_as_uint(tb[(size_t)k0 * Nn + row0 + 8]);
        qa[ks][2] = __float_as_uint(tb[(size_t)(k0 + 4) * Nn + row0]);
        qa[ks][3] = __float_as_uint(tb[(size_t)(k0 + 4) * Nn + row0 + 8]);
    }

    float o[8][4];
#pragma unroll
    for (int i = 0; i < 8; i++)
#pragma unroll
        for (int q = 0; q < 4; q++) o[i][q] = 0.f;
    float rs0 = 0.f, rs1 = 0.f;

    for (int mc = 0; mc < 16; mc++) {
        if (mc < 15) { CP_WAIT(1); } else { CP_WAIT(0); }
        __syncthreads();
        const float*    phb = phi_sm[mc & 1];
        const uint32_t* gb  = g_smh[mc & 1];

        // scores + exp + pack P to bf16 pairs
#pragma unroll
        for (int mt = 0; mt < 8; mt++) {
            float s0 = 0.f, s1 = 0.f, s2 = 0.f, s3 = 0.f;
#pragma unroll
            for (int ks = 0; ks < 2; ks++) {
                uint32_t b0 = __float_as_uint(phb[(ks*8 + t2)     * 72 + mt*8 + g4]);
                uint32_t b1 = __float_as_uint(phb[(ks*8 + t2 + 4) * 72 + mt*8 + g4]);
                MMA_TF32(s0, s1, s2, s3, qa[ks][0], qa[ks][1], qa[ks][2], qa[ks][3], b0, b1);
            }
            float p0 = ex2(s0), p1 = ex2(s1), p2 = ex2(s2), p3 = ex2(s3);
            rs0 += p0 + p1;
            rs1 += p2 + p3;
            __nv_bfloat162 h01 = __float22bfloat162_rn(make_float2(p0, p1));
            __nv_bfloat162 h23 = __float22bfloat162_rn(make_float2(p2, p3));
            p_smh[(size_t)row0       * 36 + mt * 4 + t2] = *reinterpret_cast<uint32_t*>(&h01);
            p_smh[(size_t)(row0 + 8) * 36 + mt * 4 + t2] = *reinterpret_cast<uint32_t*>(&h23);
        }
        __syncwarp();

        // O += P V  (bf16; P rows warp-private)
#pragma unroll
        for (int ms = 0; ms < 4; ms++) {
            uint32_t a0 = p_smh[(size_t)row0       * 36 + ms * 8 + t2];
            uint32_t a1 = p_smh[(size_t)(row0 + 8) * 36 + ms * 8 + t2];
            uint32_t a2 = p_smh[(size_t)row0       * 36 + ms * 8 + t2 + 4];
            uint32_t a3 = p_smh[(size_t)(row0 + 8) * 36 + ms * 8 + t2 + 4];
#pragma unroll
            for (int ct = 0; ct < 8; ct++) {
                uint32_t b0 = gb[(ct * 8 + g4) * 36 + ms * 8 + t2];
                uint32_t b1 = gb[(ct * 8 + g4) * 36 + ms * 8 + t2 + 4];
                MMA_BF16(o[ct][0], o[ct][1], o[ct][2], o[ct][3],
                         a0, a1, a2, a3, b0, b1);
            }
        }
        __syncthreads();
        if (mc + 2 < 16) issue(mc + 2, mc & 1);
    }

    rs0 += __shfl_xor_sync(0xffffffffu, rs0, 1);
    rs0 += __shfl_xor_sync(0xffffffffu, rs0, 2);
    rs1 += __shfl_xor_sync(0xffffffffu, rs1, 1);
    rs1 += __shfl_xor_sync(0xffffffffu, rs1, 2);
    const float inv0 = 1.f / rs0, inv1 = 1.f / rs1;

#pragma unroll
    for (int ct = 0; ct < 8; ct++) {
        int c = ct * 8 + 2 * t2;
        size_t base = (size_t)(b * 64 + c) * Nn + n0 + row0;
        d_obuf[base]          = o[ct][0] * inv0;
        d_obuf[base + Nn]     = o[ct][1] * inv0;
        d_obuf[base + 8]      = o[ct][2] * inv1;
        d_obuf[base + Nn + 8] = o[ct][3] * inv1;
    }
}

// ---------------------------------------------------------------------------
// Kernel 3: out = gamma * (w_o @ o) + x.
// ---------------------------------------------------------------------------
__global__ __launch_bounds__(256) void out_kernel(
    const float* __restrict__ x,
    const float* __restrict__ w_o,
    const float* __restrict__ gamma,
    float* __restrict__ out)
{
    __shared__ __align__(16) float wt_sm[64 * 128];
    __shared__ __align__(16) float o_sm [64 * 64];
    const int t  = threadIdx.x;
    const int tx = t & 15;
    const int ty = t >> 4;
    const int b   = blockIdx.y;
    const int px0 = blockIdx.x * 64;

    for (int i = t; i < 8192; i += 256) {
        int k = i & 127, c = i >> 7;
        wt_sm[c * 128 + k] = w_o[k * 64 + c];
    }
    for (int i = t; i < 1024; i += 256) {
        int c = i >> 4, p4 = i & 15;
        *(float4*)&o_sm[c * 64 + p4 * 4] =
            *(const float4*)&d_obuf[(size_t)(b * 64 + c) * Nn + px0 + p4 * 4];
    }
    __syncthreads();

    float acc[8][4];
#pragma unroll
    for (int i = 0; i < 8; i++)
#pragma unroll
        for (int q = 0; q < 4; q++) acc[i][q] = 0.f;

    const float4* o4 = (const float4*)o_sm;
    const float4* w4 = (const float4*)wt_sm;

    for (int c = 0; c < 64; c++) {
        float4 ov = o4[c * 16 + tx];
        float4 wa = w4[c * 32 + ty * 2];
        float4 wb = w4[c * 32 + ty * 2 + 1];
        const float wv[8] = {wa.x, wa.y, wa.z, wa.w, wb.x, wb.y, wb.z, wb.w};
#pragma unroll
        for (int i = 0; i < 8; i++) {
            acc[i][0] = fmaf(wv[i], ov.x, acc[i][0]);
            acc[i][1] = fmaf(wv[i], ov.y, acc[i][1]);
            acc[i][2] = fmaf(wv[i], ov.z, acc[i][2]);
            acc[i][3] = fmaf(wv[i], ov.w, acc[i][3]);
        }
    }

    const float gm = gamma[0];
#pragma unroll
    for (int i = 0; i < 8; i++) {
        size_t idx = (size_t)(b * 128 + ty * 8 + i) * Nn + px0 + tx * 4;
        float4 xv = *(const float4*)(x + idx);
        float4 rv;
        rv.x = fmaf(gm, acc[i][0], xv.x);
        rv.y = fmaf(gm, acc[i][1], xv.y);
        rv.z = fmaf(gm, acc[i][2], xv.z);
        rv.w = fmaf(gm, acc[i][3], xv.w);
        *(float4*)(out + idx) = rv;
    }
}

// ---------------------------------------------------------------------------
extern "C" void kernel_launch(void* const* d_in, const int* in_sizes, int n_in,
                              void* d_out, int out_size)
{
    const float* x       = (const float*)d_in[0];
    const float* w_theta = (const float*)d_in[1];
    const float* w_phi   = (const float*)d_in[2];
    const float* w_g     = (const float*)d_in[3];
    const float* w_o     = (const float*)d_in[4];
    const float* gamma   = (const float*)d_in[5];
    float* out = (float*)d_out;

    const int conv_smem = (96 * 132 + 2 * 32 * 136) * (int)sizeof(float);
    static bool attr_set = false;
    if (!attr_set) {
        cudaFuncSetAttribute(conv_kernel,
                             cudaFuncAttributeMaxDynamicSharedMemorySize, conv_smem);
        attr_set = true;
    }

    conv_kernel<<<dim3(32, Bz), 192, conv_smem>>>(x, w_theta, w_phi, w_g);
    attn_kernel<<<dim3(Nn / 128, Bz), 256>>>();
    out_kernel<<<dim3(Nn / 64, Bz), 256>>>(x, w_o, gamma, out);
}

// round 16
// speedup vs baseline: 1.0228x; 1.0123x over previous
#include <cuda_runtime.h>
#include <cuda_bf16.h>
#include <math_constants.h>
#include <cstdint>

#define Bz   16
#define Cch  128
#define Nn   4096
#define Mm   1024
#define LOG2E 1.4426950408889634f

// Scratch (allocation-free rule)
__device__ float d_theta[Bz * 16 * Nn];            // [B,16,N] tf32, pre-scaled by log2e
__device__ float d_phi  [Bz * 16 * Mm];            // [B,16,M] tf32
__device__ __nv_bfloat16 d_gh[Bz * 64 * Mm];       // [B,64,M] bf16
__device__ float d_obuf [Bz * 64 * Nn];            // [B,64,N] fp32

__device__ __forceinline__ float tf32r(float v) {
    uint32_t u;
    asm("cvt.rna.tf32.f32 %0, %1;" : "=r"(u) : "f"(v));
    return __uint_as_float(u);
}
__device__ __forceinline__ float ex2(float v) {
    float r;
    asm("ex2.approx.f32 %0, %1;" : "=f"(r) : "f"(v));
    return r;
}

#define CP_ASYNC16(dst_u32, src_ptr)                                          \
    asm volatile("cp.async.cg.shared.global [%0], [%1], 16;"                  \
        :: "r"(dst_u32), "l"(src_ptr))
#define CP_COMMIT() asm volatile("cp.async.commit_group;")
#define CP_WAIT(n)  asm volatile("cp.async.wait_group %0;" :: "n"(n))

#define MMA_TF32(C0,C1,C2,C3,A0,A1,A2,A3,B0,B1)                               \
    asm volatile("mma.sync.aligned.m16n8k8.row.col.f32.tf32.tf32.f32 "        \
        "{%0,%1,%2,%3}, {%4,%5,%6,%7}, {%8,%9}, {%0,%1,%2,%3};"               \
        : "+f"(C0), "+f"(C1), "+f"(C2), "+f"(C3)                              \
        : "r"(A0), "r"(A1), "r"(A2), "r"(A3), "r"(B0), "r"(B1))

#define MMA_BF16(C0,C1,C2,C3,A0,A1,A2,A3,B0,B1)                               \
    asm volatile("mma.sync.aligned.m16n8k16.row.col.f32.bf16.bf16.f32 "       \
        "{%0,%1,%2,%3}, {%4,%5,%6,%7}, {%8,%9}, {%0,%1,%2,%3};"               \
        : "+f"(C0), "+f"(C1), "+f"(C2), "+f"(C3)                              \
        : "r"(A0), "r"(A1), "r"(A2), "r"(A3), "r"(B0), "r"(B1))

// ---------------------------------------------------------------------------
// Kernel 1: 1x1 convs as tf32 mma GEMM + in-register 2x2 maxpool.
// 192 thr (6 warps), warp = m16 tile of 96 outputs, n = 128 pixels.
// K=128 in four 32-row chunks, cp.async double-buffered (issued 2 ahead).
// ---------------------------------------------------------------------------
__global__ __launch_bounds__(192) void conv_kernel(
    const float* __restrict__ x,
    const float* __restrict__ w_theta,
    const float* __restrict__ w_phi,
    const float* __restrict__ w_g)
{
    extern __shared__ __align__(16) float cs[];
    float* Ws = cs;                 // [96][132]
    float* Xs = cs + 96 * 132;      // [2][32][136]

    const int t  = threadIdx.x;
    const int b  = blockIdx.y;
    const int bx = blockIdx.x;
    const int n0 = bx * 128;

    // stage weights (theta rows pre-scaled by log2e), tf32-rounded
    for (int i = t; i < 96 * 128; i += 192) {
        int m = i >> 7, k = i & 127;
        float v;
        if (m < 16)      v = w_theta[m * 128 + k] * LOG2E;
        else if (m < 32) v = w_phi[(m - 16) * 128 + k];
        else             v = w_g[(m - 32) * 128 + k];
        Ws[m * 132 + k] = tf32r(v);
    }

    const uint32_t xs_base =
        (uint32_t)__cvta_generic_to_shared(Xs);

    // issue chunk kc (32 k-rows) into buffer buf
    auto issue = [&](int kc, int buf) {
        const float* src = x + (size_t)(b * Cch + kc * 32) * Nn + n0;
        for (int i = t; i < 32 * 32; i += 192) {      // 1024 float4
            int kk = i >> 5, p4 = i & 31;
            uint32_t dst = xs_base + (uint32_t)(buf * (32 * 136) + kk * 136 + p4 * 4) * 4u;
            CP_ASYNC16(dst, src + (size_t)kk * Nn + p4 * 4);
        }
        CP_COMMIT();
    };
    issue(0, 0);
    issue(1, 1);

    const int w    = t >> 5;
    const int lane = t & 31;
    const int g4   = lane >> 2;
    const int t2   = lane & 3;
    const int m0   = w * 16;

    float acc[16][4];
#pragma unroll
    for (int j = 0; j < 16; j++)
#pragma unroll
        for (int q = 0; q < 4; q++) acc[j][q] = 0.f;

#pragma unroll
    for (int kc = 0; kc < 4; kc++) {
        if (kc < 3) { CP_WAIT(1); } else { CP_WAIT(0); }
        __syncthreads();
        const float* Xb = Xs + (kc & 1) * (32 * 136);

#pragma unroll
        for (int ks = 0; ks < 4; ks++) {
            const int krow = kc * 32 + ks * 8;
            uint32_t a0 = __float_as_uint(Ws[(m0 + g4)     * 132 + krow + t2]);
            uint32_t a1 = __float_as_uint(Ws[(m0 + g4 + 8) * 132 + krow + t2]);
            uint32_t a2 = __float_as_uint(Ws[(m0 + g4)     * 132 + krow + t2 + 4]);
            uint32_t a3 = __float_as_uint(Ws[(m0 + g4 + 8) * 132 + krow + t2 + 4]);
#pragma unroll
            for (int j = 0; j < 16; j++) {
                uint32_t b0 = __float_as_uint(Xb[(ks * 8 + t2)     * 136 + j * 8 + g4]);
                uint32_t b1 = __float_as_uint(Xb[(ks * 8 + t2 + 4) * 136 + j * 8 + g4]);
                MMA_TF32(acc[j][0], acc[j][1], acc[j][2], acc[j][3],
                         a0, a1, a2, a3, b0, b1);
            }
        }
        __syncthreads();
        if (kc + 2 < 4) issue(kc + 2, kc & 1);
    }

    // epilogue: C[m0+g4][j*8+2t2 .. +1] = acc[j][0..1]; rows +8 -> acc[j][2..3]
    if (w == 0) {  // theta
#pragma unroll
        for (int j = 0; j < 16; j++) {
            size_t p = (size_t)(b * 16 + g4) * Nn + n0 + j * 8 + 2 * t2;
            *(float2*)&d_theta[p] = make_float2(tf32r(acc[j][0]), tf32r(acc[j][1]));
            size_t p2 = (size_t)(b * 16 + g4 + 8) * Nn + n0 + j * 8 + 2 * t2;
            *(float2*)&d_theta[p2] = make_float2(tf32r(acc[j][2]), tf32r(acc[j][3]));
        }
    } else {       // phi/g: 2x2 pool in-register
#pragma unroll
        for (int j = 0; j < 8; j++) {
            float pr0 = fmaxf(fmaxf(acc[j][0], acc[j][1]),
                              fmaxf(acc[j + 8][0], acc[j + 8][1]));
            float pr1 = fmaxf(fmaxf(acc[j][2], acc[j][3]),
                              fmaxf(acc[j + 8][2], acc[j + 8][3]));
            int pm = bx * 32 + j * 4 + t2;
            if (w == 1) {
                d_phi[(size_t)(b * 16 + g4)     * Mm + pm] = tf32r(pr0);
                d_phi[(size_t)(b * 16 + g4 + 8) * Mm + pm] = tf32r(pr1);
            } else {
                int c = (w - 2) * 16 + g4;
                d_gh[(size_t)(b * 64 + c)     * Mm + pm] = __float2bfloat16(pr0);
                d_gh[(size_t)(b * 64 + c + 8) * Mm + pm] = __float2bfloat16(pr1);
            }
        }
    }
}

// ---------------------------------------------------------------------------
// Kernel 2: attention. QK^T tf32 mma, p = ex2(s), PV bf16 m16n8k16.
// M in 16 chunks of 64, cp.async double-buffered phi/g.
// ---------------------------------------------------------------------------
__global__ __launch_bounds__(256) void attn_kernel()
{
    __shared__ __align__(16) float    phi_sm[2][16 * 72];
    __shared__ __align__(16) uint32_t g_smh [2][64 * 36];
    __shared__ __align__(16) uint32_t p_smh [128 * 36];

    const int b    = blockIdx.y;
    const int n0   = blockIdx.x * 128;
    const int t    = threadIdx.x;
    const int w    = t >> 5;
    const int lane = t & 31;
    const int g4   = lane >> 2;
    const int t2   = lane & 3;
    const int row0 = w * 16 + g4;

    const uint32_t phi_base = (uint32_t)__cvta_generic_to_shared(&phi_sm[0][0]);
    const uint32_t g_base   = (uint32_t)__cvta_generic_to_shared(&g_smh[0][0]);

    auto issue = [&](int mc, int buf) {
        // phi chunk: 16 rows x 64 floats = 256 float4
        {
            int i = t;                       // 256 threads -> exactly 1 each
            int k = i >> 4, m4 = i & 15;
            uint32_t dst = phi_base + (uint32_t)(buf * (16 * 72) + k * 72 + m4 * 4) * 4u;
            CP_ASYNC16(dst, d_phi + (size_t)(b * 16 + k) * Mm + mc * 64 + m4 * 4);
        }
        // g chunk: 64 rows x 32 u32 = 512 x 16B
        for (int i = t; i < 512; i += 256) {
            int c = i >> 3, q4 = i & 7;
            uint32_t dst = g_base + (uint32_t)(buf * (64 * 36) + c * 36 + q4 * 4) * 4u;
            CP_ASYNC16(dst, (const char*)(d_gh + (size_t)(b * 64 + c) * Mm + mc * 64) + q4 * 16);
        }
        CP_COMMIT();
    };
    issue(0, 0);
    issue(1, 1);

    // Q fragments (tf32), persist across M loop
    uint32_t qa[2][4];
    const float* tb = d_theta + (size_t)(b * 16) * Nn + n0;
#pragma unroll
    for (int ks = 0; ks < 2; ks++) {
        int k0 = ks * 8 + t2;
        qa[ks][0] = __float_as_uint(tb[(size_t)k0 * Nn + row0]);
        qa[ks][1] = __float_as_uint(tb[(size_t)k0 * Nn + row0 + 8]);
        qa[ks][2] = __float_as_uint(tb[(size_t)(k0 + 4) * Nn + row0]);
        qa[ks][3] = __float_as_uint(tb[(size_t)(k0 + 4) * Nn + row0 + 8]);
    }

    float o[8][4];
#pragma unroll
    for (int i = 0; i < 8; i++)
#pragma unroll
        for (int q = 0; q < 4; q++) o[i][q] = 0.f;
    float rs0 = 0.f, rs1 = 0.f;

    for (int mc = 0; mc < 16; mc++) {
        if (mc < 15) { CP_WAIT(1); } else { CP_WAIT(0); }
        __syncthreads();
        const float*    phb = phi_sm[mc & 1];
        const uint32_t* gb  = g_smh[mc & 1];

        // scores + exp + pack P to bf16 pairs
#pragma unroll
        for (int mt = 0; mt < 8; mt++) {
            float s0 = 0.f, s1 = 0.f, s2 = 0.f, s3 = 0.f;
#pragma unroll
            for (int ks = 0; ks < 2; ks++) {
                uint32_t b0 = __float_as_uint(phb[(ks*8 + t2)     * 72 + mt*8 + g4]);
                uint32_t b1 = __float_as_uint(phb[(ks*8 + t2 + 4) * 72 + mt*8 + g4]);
                MMA_TF32(s0, s1, s2, s3, qa[ks][0], qa[ks][1], qa[ks][2], qa[ks][3], b0, b1);
            }
            float p0 = ex2(s0), p1 = ex2(s1), p2 = ex2(s2), p3 = ex2(s3);
            rs0 += p0 + p1;
            rs1 += p2 + p3;
            __nv_bfloat162 h01 = __float22bfloat162_rn(make_float2(p0, p1));
            __nv_bfloat162 h23 = __float22bfloat162_rn(make_float2(p2, p3));
            p_smh[(size_t)row0       * 36 + mt * 4 + t2] = *reinterpret_cast<uint32_t*>(&h01);
            p_smh[(size_t)(row0 + 8) * 36 + mt * 4 + t2] = *reinterpret_cast<uint32_t*>(&h23);
        }
        __syncwarp();

        // O += P V  (bf16; P rows warp-private)
#pragma unroll
        for (int ms = 0; ms < 4; ms++) {
            uint32_t a0 = p_smh[(size_t)row0       * 36 + ms * 8 + t2];
            uint32_t a1 = p_smh[(size_t)(row0 + 8) * 36 + ms * 8 + t2];
            uint32_t a2 = p_smh[(size_t)row0       * 36 + ms * 8 + t2 + 4];
            uint32_t a3 = p_smh[(size_t)(row0 + 8) * 36 + ms * 8 + t2 + 4];
#pragma unroll
            for (int ct = 0; ct < 8; ct++) {
                uint32_t b0 = gb[(ct * 8 + g4) * 36 + ms * 8 + t2];
                uint32_t b1 = gb[(ct * 8 + g4) * 36 + ms * 8 + t2 + 4];
                MMA_BF16(o[ct][0], o[ct][1], o[ct][2], o[ct][3],
                         a0, a1, a2, a3, b0, b1);
            }
        }
        __syncthreads();
        if (mc + 2 < 16) issue(mc + 2, mc & 1);
    }

    rs0 += __shfl_xor_sync(0xffffffffu, rs0, 1);
    rs0 += __shfl_xor_sync(0xffffffffu, rs0, 2);
    rs1 += __shfl_xor_sync(0xffffffffu, rs1, 1);
    rs1 += __shfl_xor_sync(0xffffffffu, rs1, 2);
    const float inv0 = 1.f / rs0, inv1 = 1.f / rs1;

#pragma unroll
    for (int ct = 0; ct < 8; ct++) {
        int c = ct * 8 + 2 * t2;
        size_t base = (size_t)(b * 64 + c) * Nn + n0 + row0;
        d_obuf[base]          = o[ct][0] * inv0;
        d_obuf[base + Nn]     = o[ct][1] * inv0;
        d_obuf[base + 8]      = o[ct][2] * inv1;
        d_obuf[base + Nn + 8] = o[ct][3] * inv1;
    }
}

// ---------------------------------------------------------------------------
// Kernel 3: out = gamma * (w_o @ o) + x.
// ---------------------------------------------------------------------------
__global__ __launch_bounds__(256) void out_kernel(
    const float* __restrict__ x,
    const float* __restrict__ w_o,
    const float* __restrict__ gamma,
    float* __restrict__ out)
{
    __shared__ __align__(16) float wt_sm[64 * 128];
    __shared__ __align__(16) float o_sm [64 * 64];
    const int t  = threadIdx.x;
    const int tx = t & 15;
    const int ty = t >> 4;
    const int b   = blockIdx.y;
    const int px0 = blockIdx.x * 64;

    for (int i = t; i < 8192; i += 256) {
        int k = i & 127, c = i >> 7;
        wt_sm[c * 128 + k] = w_o[k * 64 + c];
    }
    for (int i = t; i < 1024; i += 256) {
        int c = i >> 4, p4 = i & 15;
        *(float4*)&o_sm[c * 64 + p4 * 4] =
            *(const float4*)&d_obuf[(size_t)(b * 64 + c) * Nn + px0 + p4 * 4];
    }
    __syncthreads();

    float acc[8][4];
#pragma unroll
    for (int i = 0; i < 8; i++)
#pragma unroll
        for (int q = 0; q < 4; q++) acc[i][q] = 0.f;

    const float4* o4 = (const float4*)o_sm;
    const float4* w4 = (const float4*)wt_sm;

    for (int c = 0; c < 64; c++) {
        float4 ov = o4[c * 16 + tx];
        float4 wa = w4[c * 32 + ty * 2];
        float4 wb = w4[c * 32 + ty * 2 + 1];
        const float wv[8] = {wa.x, wa.y, wa.z, wa.w, wb.x, wb.y, wb.z, wb.w};
#pragma unroll
        for (int i = 0; i < 8; i++) {
            acc[i][0] = fmaf(wv[i], ov.x, acc[i][0]);
            acc[i][1] = fmaf(wv[i], ov.y, acc[i][1]);
            acc[i][2] = fmaf(wv[i], ov.z, acc[i][2]);
            acc[i][3] = fmaf(wv[i], ov.w, acc[i][3]);
        }
    }

    const float gm = gamma[0];
#pragma unroll
    for (int i = 0; i < 8; i++) {
        size_t idx = (size_t)(b * 128 + ty * 8 + i) * Nn + px0 + tx * 4;
        float4 xv = *(const float4*)(x + idx);
        float4 rv;
        rv.x = fmaf(gm, acc[i][0], xv.x);
        rv.y = fmaf(gm, acc[i][1], xv.y);
        rv.z = fmaf(gm, acc[i][2], xv.z);
        rv.w = fmaf(gm, acc[i][3], xv.w);
        *(float4*)(out + idx) = rv;
    }
}

// ---------------------------------------------------------------------------
extern "C" void kernel_launch(void* const* d_in, const int* in_sizes, int n_in,
                              void* d_out, int out_size)
{
    const float* x       = (const float*)d_in[0];
    const float* w_theta = (const float*)d_in[1];
    const float* w_phi   = (const float*)d_in[2];
    const float* w_g     = (const float*)d_in[3];
    const float* w_o     = (const float*)d_in[4];
    const float* gamma   = (const float*)d_in[5];
    float* out = (float*)d_out;

    const int conv_smem = (96 * 132 + 2 * 32 * 136) * (int)sizeof(float);
    static bool attr_set = false;
    if (!attr_set) {
        cudaFuncSetAttribute(conv_kernel,
                             cudaFuncAttributeMaxDynamicSharedMemorySize, conv_smem);
        attr_set = true;
    }

    conv_kernel<<<dim3(32, Bz), 192, conv_smem>>>(x, w_theta, w_phi, w_g);
    attn_kernel<<<dim3(Nn / 128, Bz), 256>>>();
    out_kernel<<<dim3(Nn / 64, Bz), 256>>>(x, w_o, gamma, out);
}